// round 9
// baseline (speedup 1.0000x reference)
#include <cuda_runtime.h>
#include <cuda_bf16.h>
#include <cstdint>
#include <math.h>

// ---------------- problem constants ----------------
#define NTOK 8192      // B*T
#define DIMD 1024
#define NEXP 8
#define HID  2816
#define NPAIR (2*NTOK)
#define WN   ((size_t)NEXP*HID*DIMD)

// ---------------- device scratch (static; allocations forbidden) ----------------
__device__ __nv_bfloat16 g_w1h[WN], g_w1l[WN];
__device__ __nv_bfloat16 g_w3h[WN], g_w3l[WN];
__device__ __nv_bfloat16 g_w2h[WN], g_w2l[WN];
__device__ __nv_bfloat16 g_xh[(size_t)NTOK*DIMD], g_xl[(size_t)NTOK*DIMD];
__device__ __nv_bfloat16 g_hh[(size_t)NPAIR*HID], g_hl[(size_t)NPAIR*HID];
__device__ float g_pout[(size_t)NPAIR*DIMD];
__device__ int   g_list[NEXP*NTOK];
__device__ float g_wt[NPAIR];
__device__ int   g_cnt[NEXP];

// ---------------- PTX helpers (base PTX only: sm_80+ features) ----------------
static __device__ __forceinline__ uint32_t smem_u32(const void* p) {
    uint32_t a;
    asm("{ .reg .u64 t; cvta.to.shared.u64 t, %1; cvt.u32.u64 %0, t; }" : "=r"(a) : "l"(p));
    return a;
}
static __device__ __forceinline__ void cpa(uint32_t dst, const void* src) {
    asm volatile("cp.async.cg.shared.global [%0], [%1], 16;" :: "r"(dst), "l"(src) : "memory");
}
#define CPA_COMMIT() asm volatile("cp.async.commit_group;" ::: "memory")
#define CPA_WAIT1()  asm volatile("cp.async.wait_group 1;" ::: "memory")
#define CPA_WAIT0()  asm volatile("cp.async.wait_group 0;" ::: "memory")

static __device__ __forceinline__ void ldm_x4(uint32_t a, uint32_t* r) {
    asm volatile("ldmatrix.sync.aligned.m8n8.x4.shared.b16 {%0,%1,%2,%3}, [%4];"
        : "=r"(r[0]), "=r"(r[1]), "=r"(r[2]), "=r"(r[3]) : "r"(a));
}
static __device__ __forceinline__ void mma16816(float* c, const uint32_t* a, const uint32_t* b) {
    asm volatile("mma.sync.aligned.m16n8k16.row.col.f32.bf16.bf16.f32 "
        "{%0,%1,%2,%3}, {%4,%5,%6,%7}, {%8,%9}, {%0,%1,%2,%3};"
        : "+f"(c[0]), "+f"(c[1]), "+f"(c[2]), "+f"(c[3])
        : "r"(a[0]), "r"(a[1]), "r"(a[2]), "r"(a[3]), "r"(b[0]), "r"(b[1]));
}
static __device__ __forceinline__ uint32_t pack2(__nv_bfloat16 a, __nv_bfloat16 b) {
    return (uint32_t)__bfloat16_as_ushort(a) | ((uint32_t)__bfloat16_as_ushort(b) << 16);
}

// smem row stride: 72 bf16 = 144B. Rows rotate 16B mod 128B -> ldmatrix conflict-free.
#define RS 144

// Unified GEMM geometry (both stages): CTA M=128 x N=256 (B-tile rows),
// 8 warps as 2(M) x 4(N): warp tile 64M x 64N (mt=4, nt=8). K-chunk 64, 2-buf.
#define OFF_AH 0
#define OFF_AL 18432
#define OFF_BH 36864
#define OFF_BL 73728
#define BUFSZ  110592
#define SMEM_TOTAL (1024 + 2*BUFSZ)   // 222208

// ---------------- small kernels ----------------
__global__ void init_kernel() {
    if (threadIdx.x < NEXP) g_cnt[threadIdx.x] = 0;
}

__global__ void cvt_kernel(const float* __restrict__ src,
                           __nv_bfloat16* __restrict__ hi,
                           __nv_bfloat16* __restrict__ lo, int n4) {
    int i = blockIdx.x * blockDim.x + threadIdx.x;
    if (i >= n4) return;
    float4 v = reinterpret_cast<const float4*>(src)[i];
    __nv_bfloat16 h0 = __float2bfloat16(v.x), h1 = __float2bfloat16(v.y);
    __nv_bfloat16 h2 = __float2bfloat16(v.z), h3 = __float2bfloat16(v.w);
    __nv_bfloat16 l0 = __float2bfloat16(v.x - __bfloat162float(h0));
    __nv_bfloat16 l1 = __float2bfloat16(v.y - __bfloat162float(h1));
    __nv_bfloat16 l2 = __float2bfloat16(v.z - __bfloat162float(h2));
    __nv_bfloat16 l3 = __float2bfloat16(v.w - __bfloat162float(h3));
    uint2 H; H.x = pack2(h0, h1); H.y = pack2(h2, h3);
    uint2 L; L.x = pack2(l0, l1); L.y = pack2(l2, l3);
    reinterpret_cast<uint2*>(hi)[i] = H;
    reinterpret_cast<uint2*>(lo)[i] = L;
}

__global__ void router_kernel(const float* __restrict__ x,
                              const float* __restrict__ gw) {
    int w    = (blockIdx.x * blockDim.x + threadIdx.x) >> 5;
    int lane = threadIdx.x & 31;
    if (w >= NTOK) return;
    const float* xr = x + (size_t)w * DIMD;
    float acc[NEXP];
#pragma unroll
    for (int e = 0; e < NEXP; e++) acc[e] = 0.f;
    for (int d = lane; d < DIMD; d += 32) {
        float xv = xr[d];
#pragma unroll
        for (int e = 0; e < NEXP; e++) acc[e] += xv * gw[e * DIMD + d];
    }
#pragma unroll
    for (int e = 0; e < NEXP; e++)
#pragma unroll
        for (int o = 16; o > 0; o >>= 1)
            acc[e] += __shfl_xor_sync(0xffffffffu, acc[e], o);
    if (lane == 0) {
        float m = acc[0];
#pragma unroll
        for (int e = 1; e < NEXP; e++) m = fmaxf(m, acc[e]);
        float p[NEXP];
#pragma unroll
        for (int e = 0; e < NEXP; e++) p[e] = __expf(acc[e] - m);
        int i0 = 0; float b0 = p[0];
#pragma unroll
        for (int e = 1; e < NEXP; e++) if (p[e] > b0) { b0 = p[e]; i0 = e; }
        int i1 = -1; float b1 = -1.f;
#pragma unroll
        for (int e = 0; e < NEXP; e++) if (e != i0 && p[e] > b1) { b1 = p[e]; i1 = e; }
        float s = b0 + b1;
        g_wt[2 * w]     = b0 / s;
        g_wt[2 * w + 1] = b1 / s;
        int pos0 = atomicAdd(&g_cnt[i0], 1);
        g_list[i0 * NTOK + pos0] = 2 * w;
        int pos1 = atomicAdd(&g_cnt[i1], 1);
        g_list[i1 * NTOK + pos1] = 2 * w + 1;
    }
}

extern __shared__ char dynsmem[];

// =======================================================================
// Stage A: single GEMM with w1/w3 rows interleaved in the B tile.
// MMA issue order interleaves all 4 mt x 2 cols (8 independent accumulators)
// within each of the 3 split-passes -> same-acc reuse distance = 8 mmas.
// =======================================================================
__global__ __launch_bounds__(256, 1) void ffn1_mma() {
    int e   = blockIdx.z;
    int cnt = g_cnt[e];
    int m0  = blockIdx.y * 128;
    if (m0 >= cnt) return;
    int n0h = blockIdx.x * 128;   // hidden base

    int* s_rows = reinterpret_cast<int*>(dynsmem);
    uint32_t sb = smem_u32(dynsmem) + 1024;

    int tid = threadIdx.x, lane = tid & 31, wid = tid >> 5;
    if (tid < 128) s_rows[tid] = g_list[e * NTOK + min(m0 + tid, cnt - 1)];
    __syncthreads();

    const __nv_bfloat16* W1h = g_w1h + (size_t)e * HID * DIMD;
    const __nv_bfloat16* W1l = g_w1l + (size_t)e * HID * DIMD;
    const __nv_bfloat16* W3h = g_w3h + (size_t)e * HID * DIMD;
    const __nv_bfloat16* W3l = g_w3l + (size_t)e * HID * DIMD;

    float acc[4][8][4];
#pragma unroll
    for (int mt = 0; mt < 4; mt++)
#pragma unroll
        for (int nt = 0; nt < 8; nt++)
#pragma unroll
            for (int q = 0; q < 4; q++) acc[mt][nt][q] = 0.f;

    int wm = (wid >> 2) * 64;
    int wn = (wid & 3) * 64;     // B-tile col offset (= 32 hidden)

    auto load_chunk = [&](uint32_t bb, int k0) {
#pragma unroll
        for (int it = 0; it < 4; it++) {         // A: 128 rows
            int i = tid + it * 256;
            int r = i >> 3, c = i & 7;
            int tok = s_rows[r] >> 1;
            size_t off = (size_t)tok * DIMD + k0 + c * 8;
            cpa(bb + OFF_AH + r * RS + c * 16, g_xh + off);
            cpa(bb + OFF_AL + r * RS + c * 16, g_xl + off);
        }
#pragma unroll
        for (int it = 0; it < 8; it++) {         // B: 256 interleaved rows
            int i = tid + it * 256;
            int r = i >> 3, c = i & 7;
            int j = n0h + (r >> 1);
            const __nv_bfloat16* sh = (r & 1) ? W3h : W1h;
            const __nv_bfloat16* sl = (r & 1) ? W3l : W1l;
            size_t off = (size_t)j * DIMD + k0 + c * 8;
            cpa(bb + OFF_BH + r * RS + c * 16, sh + off);
            cpa(bb + OFF_BL + r * RS + c * 16, sl + off);
        }
        CPA_COMMIT();
    };

    load_chunk(sb, 0);

    for (int kc = 0; kc < DIMD / 64; kc++) {
        uint32_t bb = sb + (kc & 1) * BUFSZ;
        if (kc + 1 < DIMD / 64) {
            load_chunk(sb + ((kc + 1) & 1) * BUFSZ, (kc + 1) * 64);
            CPA_WAIT1();
        } else {
            CPA_WAIT0();
        }
        __syncthreads();

#pragma unroll
        for (int ks = 0; ks < 4; ks++) {
            uint32_t ah[4][4], al[4][4];
            int arow = wm + (lane & 15);
            int acol = ks * 16 + ((lane >> 4) << 3);
#pragma unroll
            for (int mt = 0; mt < 4; mt++) {
                uint32_t ao = (uint32_t)((arow + mt * 16) * RS + acol * 2);
                ldm_x4(bb + OFF_AH + ao, ah[mt]);
                ldm_x4(bb + OFF_AL + ao, al[mt]);
            }
            int brow = wn + (lane & 7) + ((lane >> 4) << 3);
            int bcol = ks * 16 + ((lane >> 3) & 1) * 8;
#pragma unroll
            for (int ntp = 0; ntp < 4; ntp++) {
                uint32_t bo = (uint32_t)((brow + ntp * 16) * RS + bcol * 2);
                uint32_t bh4[4], bl4[4];
                ldm_x4(bb + OFF_BH + bo, bh4);
                ldm_x4(bb + OFF_BL + bo, bl4);
                // pass 1: ah x bh  (8 independent accs)
#pragma unroll
                for (int mt = 0; mt < 4; mt++) mma16816(acc[mt][2*ntp],   ah[mt], bh4);
#pragma unroll
                for (int mt = 0; mt < 4; mt++) mma16816(acc[mt][2*ntp+1], ah[mt], bh4 + 2);
                // pass 2: ah x bl
#pragma unroll
                for (int mt = 0; mt < 4; mt++) mma16816(acc[mt][2*ntp],   ah[mt], bl4);
#pragma unroll
                for (int mt = 0; mt < 4; mt++) mma16816(acc[mt][2*ntp+1], ah[mt], bl4 + 2);
                // pass 3: al x bh
#pragma unroll
                for (int mt = 0; mt < 4; mt++) mma16816(acc[mt][2*ntp],   al[mt], bh4);
#pragma unroll
                for (int mt = 0; mt < 4; mt++) mma16816(acc[mt][2*ntp+1], al[mt], bh4 + 2);
            }
        }
        __syncthreads();
    }

    // epilogue: c0=w1-dot (even col), c1=w3-dot (odd col), same hidden index.
    uint32_t* HH = reinterpret_cast<uint32_t*>(g_hh);
    uint32_t* HL = reinterpret_cast<uint32_t*>(g_hl);
    int hb = n0h + (wn >> 1) + (lane & 3);   // + nt*4 below
#pragma unroll
    for (int mt = 0; mt < 4; mt++) {
#pragma unroll
        for (int half = 0; half < 2; half++) {
            int mi = wm + mt * 16 + (lane >> 2) + half * 8;
            bool valid = (m0 + mi) < cnt;
            int slot = s_rows[mi];
#pragma unroll
            for (int nt = 0; nt < 8; nt++) {
                float c0 = acc[mt][nt][half * 2];
                float c1 = acc[mt][nt][half * 2 + 1];
                float h = c0 / (1.f + __expf(-c0)) * c1;
                __nv_bfloat16 Hh = __float2bfloat16(h);
                __nv_bfloat16 Lh = __float2bfloat16(h - __bfloat162float(Hh));
                uint32_t hl = pack2(Hh, Lh);
                uint32_t other = __shfl_xor_sync(0xffffffffu, hl, 1);
                if (!(lane & 1) && valid) {
                    int hidden = hb + nt * 4;            // even
                    size_t idx = ((size_t)slot * HID + hidden) >> 1;
                    HH[idx] = (hl & 0xffffu) | ((other & 0xffffu) << 16);
                    HL[idx] = (hl >> 16) | (other & 0xffff0000u);
                }
            }
        }
    }
}

// =======================================================================
// Stage B: pout = (h @ w2^T) * wt.  Same geometry + same reordered issue.
// =======================================================================
__global__ __launch_bounds__(256, 1) void ffn2_mma() {
    int e   = blockIdx.z;
    int cnt = g_cnt[e];
    int m0  = blockIdx.y * 128;
    if (m0 >= cnt) return;
    int n0  = blockIdx.x * 256;

    int* s_rows = reinterpret_cast<int*>(dynsmem);
    uint32_t sb = smem_u32(dynsmem) + 1024;

    int tid = threadIdx.x, lane = tid & 31, wid = tid >> 5;
    if (tid < 128) s_rows[tid] = g_list[e * NTOK + min(m0 + tid, cnt - 1)];
    __syncthreads();

    const __nv_bfloat16* W2h = g_w2h + (size_t)e * DIMD * HID;
    const __nv_bfloat16* W2l = g_w2l + (size_t)e * DIMD * HID;

    float acc[4][8][4];
#pragma unroll
    for (int mt = 0; mt < 4; mt++)
#pragma unroll
        for (int nt = 0; nt < 8; nt++)
#pragma unroll
            for (int q = 0; q < 4; q++) acc[mt][nt][q] = 0.f;

    int wm = (wid >> 2) * 64;
    int wn = (wid & 3) * 64;

    auto load_chunk = [&](uint32_t bb, int k0) {
#pragma unroll
        for (int it = 0; it < 4; it++) {         // A: 128 rows (gathered h)
            int i = tid + it * 256;
            int r = i >> 3, c = i & 7;
            int slot = s_rows[r];
            size_t off = (size_t)slot * HID + k0 + c * 8;
            cpa(bb + OFF_AH + r * RS + c * 16, g_hh + off);
            cpa(bb + OFF_AL + r * RS + c * 16, g_hl + off);
        }
#pragma unroll
        for (int it = 0; it < 8; it++) {         // B: 256 w2 rows
            int i = tid + it * 256;
            int r = i >> 3, c = i & 7;
            size_t off = (size_t)(n0 + r) * HID + k0 + c * 8;
            cpa(bb + OFF_BH + r * RS + c * 16, W2h + off);
            cpa(bb + OFF_BL + r * RS + c * 16, W2l + off);
        }
        CPA_COMMIT();
    };

    load_chunk(sb, 0);

    for (int kc = 0; kc < HID / 64; kc++) {
        uint32_t bb = sb + (kc & 1) * BUFSZ;
        if (kc + 1 < HID / 64) {
            load_chunk(sb + ((kc + 1) & 1) * BUFSZ, (kc + 1) * 64);
            CPA_WAIT1();
        } else {
            CPA_WAIT0();
        }
        __syncthreads();

#pragma unroll
        for (int ks = 0; ks < 4; ks++) {
            uint32_t ah[4][4], al[4][4];
            int arow = wm + (lane & 15);
            int acol = ks * 16 + ((lane >> 4) << 3);
#pragma unroll
            for (int mt = 0; mt < 4; mt++) {
                uint32_t ao = (uint32_t)((arow + mt * 16) * RS + acol * 2);
                ldm_x4(bb + OFF_AH + ao, ah[mt]);
                ldm_x4(bb + OFF_AL + ao, al[mt]);
            }
            int brow = wn + (lane & 7) + ((lane >> 4) << 3);
            int bcol = ks * 16 + ((lane >> 3) & 1) * 8;
#pragma unroll
            for (int ntp = 0; ntp < 4; ntp++) {
                uint32_t bo = (uint32_t)((brow + ntp * 16) * RS + bcol * 2);
                uint32_t bh4[4], bl4[4];
                ldm_x4(bb + OFF_BH + bo, bh4);
                ldm_x4(bb + OFF_BL + bo, bl4);
                // pass 1: ah x bh
#pragma unroll
                for (int mt = 0; mt < 4; mt++) mma16816(acc[mt][2*ntp],   ah[mt], bh4);
#pragma unroll
                for (int mt = 0; mt < 4; mt++) mma16816(acc[mt][2*ntp+1], ah[mt], bh4 + 2);
                // pass 2: ah x bl
#pragma unroll
                for (int mt = 0; mt < 4; mt++) mma16816(acc[mt][2*ntp],   ah[mt], bl4);
#pragma unroll
                for (int mt = 0; mt < 4; mt++) mma16816(acc[mt][2*ntp+1], ah[mt], bl4 + 2);
                // pass 3: al x bh
#pragma unroll
                for (int mt = 0; mt < 4; mt++) mma16816(acc[mt][2*ntp],   al[mt], bh4);
#pragma unroll
                for (int mt = 0; mt < 4; mt++) mma16816(acc[mt][2*ntp+1], al[mt], bh4 + 2);
            }
        }
        __syncthreads();
    }

    // epilogue: pout = acc * wt[slot]
#pragma unroll
    for (int mt = 0; mt < 4; mt++) {
#pragma unroll
        for (int half = 0; half < 2; half++) {
            int mi = wm + mt * 16 + (lane >> 2) + half * 8;
            if (m0 + mi >= cnt) continue;
            int slot = s_rows[mi];
            float wt = g_wt[slot];
            float* row = g_pout + (size_t)slot * DIMD;
#pragma unroll
            for (int nt = 0; nt < 8; nt++) {
                int gn = n0 + wn + nt * 8 + 2 * (lane & 3);
                float2 v;
                v.x = acc[mt][nt][half * 2] * wt;
                v.y = acc[mt][nt][half * 2 + 1] * wt;
                *reinterpret_cast<float2*>(row + gn) = v;
            }
        }
    }
}

// ---------------- combine ----------------
__global__ void combine_kernel(float* __restrict__ out) {
    size_t i = (size_t)blockIdx.x * blockDim.x + threadIdx.x;
    const size_t Q = DIMD / 4;
    if (i < (size_t)NTOK * Q) {
        size_t t = i / Q, q = i % Q;
        const float4* p = reinterpret_cast<const float4*>(g_pout);
        float4 a = p[(2 * t) * Q + q];
        float4 b = p[(2 * t + 1) * Q + q];
        float4 o;
        o.x = a.x + b.x; o.y = a.y + b.y; o.z = a.z + b.z; o.w = a.w + b.w;
        reinterpret_cast<float4*>(out)[i] = o;
    }
}

// ---------------- launcher ----------------
extern "C" void kernel_launch(void* const* d_in, const int* in_sizes, int n_in,
                              void* d_out, int out_size) {
    const float* x  = (const float*)d_in[0];
    const float* gw = (const float*)d_in[1];
    const float* w1 = (const float*)d_in[2];
    const float* w3 = (const float*)d_in[3];
    const float* w2 = (const float*)d_in[4];
    float* out = (float*)d_out;

    __nv_bfloat16 *xh, *xl, *w1h, *w1l, *w3h, *w3l, *w2h, *w2l;
    cudaGetSymbolAddress((void**)&xh,  g_xh);  cudaGetSymbolAddress((void**)&xl,  g_xl);
    cudaGetSymbolAddress((void**)&w1h, g_w1h); cudaGetSymbolAddress((void**)&w1l, g_w1l);
    cudaGetSymbolAddress((void**)&w3h, g_w3h); cudaGetSymbolAddress((void**)&w3l, g_w3l);
    cudaGetSymbolAddress((void**)&w2h, g_w2h); cudaGetSymbolAddress((void**)&w2l, g_w2l);

    cudaFuncSetAttribute(ffn1_mma, cudaFuncAttributeMaxDynamicSharedMemorySize, SMEM_TOTAL);
    cudaFuncSetAttribute(ffn2_mma, cudaFuncAttributeMaxDynamicSharedMemorySize, SMEM_TOTAL);

    init_kernel<<<1, 32>>>();
    router_kernel<<<NTOK / 8, 256>>>(x, gw);

    int xn4 = NTOK * DIMD / 4;
    int wn4 = (int)(WN / 4);
    cvt_kernel<<<(xn4 + 255) / 256, 256>>>(x,  xh,  xl,  xn4);
    cvt_kernel<<<(wn4 + 255) / 256, 256>>>(w1, w1h, w1l, wn4);
    cvt_kernel<<<(wn4 + 255) / 256, 256>>>(w3, w3h, w3l, wn4);
    cvt_kernel<<<(wn4 + 255) / 256, 256>>>(w2, w2h, w2l, wn4);

    ffn1_mma<<<dim3(HID / 128, NTOK / 128, NEXP), 256, SMEM_TOTAL>>>();
    ffn2_mma<<<dim3(DIMD / 256, NTOK / 128, NEXP), 256, SMEM_TOTAL>>>();
    combine_kernel<<<(NTOK * (DIMD / 4) + 255) / 256, 256>>>(out);
}

// round 12
// speedup vs baseline: 1.3992x; 1.3992x over previous
#include <cuda_runtime.h>
#include <cuda_fp16.h>
#include <cstdint>
#include <math.h>

// ---------------- problem constants ----------------
#define NTOK 8192      // B*T
#define DIMD 1024
#define NEXP 8
#define HID  2816
#define NPAIR (2*NTOK)
#define WN   ((size_t)NEXP*HID*DIMD)

// ---------------- device scratch (static; allocations forbidden) ----------------
__device__ __half g_w1f[WN], g_w3f[WN], g_w2f[WN];                  // fp16 weights
__device__ __half g_xh[(size_t)NTOK*DIMD], g_xl[(size_t)NTOK*DIMD]; // x hi/lo
__device__ __half g_hh[(size_t)NPAIR*HID], g_hl[(size_t)NPAIR*HID]; // h hi/lo
__device__ float g_pout[(size_t)NPAIR*DIMD];
__device__ int   g_list[NEXP*NTOK];
__device__ float g_wt[NPAIR];
__device__ int   g_cnt[NEXP];

// ---------------- PTX helpers (base PTX only: sm_80+ features) ----------------
static __device__ __forceinline__ uint32_t smem_u32(const void* p) {
    uint32_t a;
    asm("{ .reg .u64 t; cvta.to.shared.u64 t, %1; cvt.u32.u64 %0, t; }" : "=r"(a) : "l"(p));
    return a;
}
static __device__ __forceinline__ void cpa(uint32_t dst, const void* src) {
    asm volatile("cp.async.cg.shared.global [%0], [%1], 16;" :: "r"(dst), "l"(src) : "memory");
}
#define CPA_COMMIT() asm volatile("cp.async.commit_group;" ::: "memory")
#define CPA_WAIT1()  asm volatile("cp.async.wait_group 1;" ::: "memory")
#define CPA_WAIT0()  asm volatile("cp.async.wait_group 0;" ::: "memory")

static __device__ __forceinline__ void ldm_x4(uint32_t a, uint32_t* r) {
    asm volatile("ldmatrix.sync.aligned.m8n8.x4.shared.b16 {%0,%1,%2,%3}, [%4];"
        : "=r"(r[0]), "=r"(r[1]), "=r"(r[2]), "=r"(r[3]) : "r"(a));
}
static __device__ __forceinline__ void mma16816(float* c, const uint32_t* a, const uint32_t* b) {
    asm volatile("mma.sync.aligned.m16n8k16.row.col.f32.f16.f16.f32 "
        "{%0,%1,%2,%3}, {%4,%5,%6,%7}, {%8,%9}, {%0,%1,%2,%3};"
        : "+f"(c[0]), "+f"(c[1]), "+f"(c[2]), "+f"(c[3])
        : "r"(a[0]), "r"(a[1]), "r"(a[2]), "r"(a[3]), "r"(b[0]), "r"(b[1]));
}
static __device__ __forceinline__ uint32_t pack2h(__half a, __half b) {
    return (uint32_t)__half_as_ushort(a) | ((uint32_t)__half_as_ushort(b) << 16);
}

// smem row stride: 72 fp16 = 144B. Rows rotate 16B mod 128B -> ldmatrix conflict-free.
#define RS 144

// Unified GEMM geometry: CTA M=128 x N=256 (B-tile rows), 8 warps as 2(M)x4(N):
// warp tile 64M x 64N (mt=4, nt=8). K-chunk 64, double-buffered.
// A: hi+lo (2 x 18432), B: single fp16 (36864).
#define OFF_AH 0
#define OFF_AL 18432
#define OFF_B  36864
#define BUFSZ  73728
#define SMEM_TOTAL (1024 + 2*BUFSZ)   // 148480

// ---------------- small kernels ----------------
__global__ void init_kernel() {
    if (threadIdx.x < NEXP) g_cnt[threadIdx.x] = 0;
}

// x (and any A-side tensor): split fp32 -> fp16 hi + fp16 lo
__global__ void cvt_x_kernel(const float* __restrict__ src,
                             __half* __restrict__ hi,
                             __half* __restrict__ lo, int n4) {
    int i = blockIdx.x * blockDim.x + threadIdx.x;
    if (i >= n4) return;
    float4 v = reinterpret_cast<const float4*>(src)[i];
    __half h0 = __float2half_rn(v.x), h1 = __float2half_rn(v.y);
    __half h2 = __float2half_rn(v.z), h3 = __float2half_rn(v.w);
    __half l0 = __float2half_rn(v.x - __half2float(h0));
    __half l1 = __float2half_rn(v.y - __half2float(h1));
    __half l2 = __float2half_rn(v.z - __half2float(h2));
    __half l3 = __float2half_rn(v.w - __half2float(h3));
    uint2 H; H.x = pack2h(h0, h1); H.y = pack2h(h2, h3);
    uint2 L; L.x = pack2h(l0, l1); L.y = pack2h(l2, l3);
    reinterpret_cast<uint2*>(hi)[i] = H;
    reinterpret_cast<uint2*>(lo)[i] = L;
}

// weights: fp32 -> single fp16; z=0 -> (s0,d0), z=1 -> (s1,d1)
__global__ void cvt_w2x_kernel(const float* __restrict__ s0, __half* __restrict__ d0,
                               const float* __restrict__ s1, __half* __restrict__ d1,
                               int n4) {
    int i = blockIdx.x * blockDim.x + threadIdx.x;
    if (i >= n4) return;
    const float* src = blockIdx.z ? s1 : s0;
    __half* dst = blockIdx.z ? d1 : d0;
    float4 v = reinterpret_cast<const float4*>(src)[i];
    uint2 H;
    H.x = pack2h(__float2half_rn(v.x), __float2half_rn(v.y));
    H.y = pack2h(__float2half_rn(v.z), __float2half_rn(v.w));
    reinterpret_cast<uint2*>(dst)[i] = H;
}

__global__ void router_kernel(const float* __restrict__ x,
                              const float* __restrict__ gw) {
    int w    = (blockIdx.x * blockDim.x + threadIdx.x) >> 5;
    int lane = threadIdx.x & 31;
    if (w >= NTOK) return;
    const float* xr = x + (size_t)w * DIMD;
    float acc[NEXP];
#pragma unroll
    for (int e = 0; e < NEXP; e++) acc[e] = 0.f;
    for (int d = lane; d < DIMD; d += 32) {
        float xv = xr[d];
#pragma unroll
        for (int e = 0; e < NEXP; e++) acc[e] += xv * gw[e * DIMD + d];
    }
#pragma unroll
    for (int e = 0; e < NEXP; e++)
#pragma unroll
        for (int o = 16; o > 0; o >>= 1)
            acc[e] += __shfl_xor_sync(0xffffffffu, acc[e], o);
    if (lane == 0) {
        float m = acc[0];
#pragma unroll
        for (int e = 1; e < NEXP; e++) m = fmaxf(m, acc[e]);
        float p[NEXP];
#pragma unroll
        for (int e = 0; e < NEXP; e++) p[e] = __expf(acc[e] - m);
        int i0 = 0; float b0 = p[0];
#pragma unroll
        for (int e = 1; e < NEXP; e++) if (p[e] > b0) { b0 = p[e]; i0 = e; }
        int i1 = -1; float b1 = -1.f;
#pragma unroll
        for (int e = 0; e < NEXP; e++) if (e != i0 && p[e] > b1) { b1 = p[e]; i1 = e; }
        float s = b0 + b1;
        g_wt[2 * w]     = b0 / s;
        g_wt[2 * w + 1] = b1 / s;
        int pos0 = atomicAdd(&g_cnt[i0], 1);
        g_list[i0 * NTOK + pos0] = 2 * w;
        int pos1 = atomicAdd(&g_cnt[i1], 1);
        g_list[i1 * NTOK + pos1] = 2 * w + 1;
    }
}

extern __shared__ char dynsmem[];

// =======================================================================
// Stage A: single GEMM, w1/w3 rows interleaved in B tile (fp16 single).
// 2 passes: ah x b, al x b  (A = x split hi/lo; weight-quant error only).
// =======================================================================
__global__ __launch_bounds__(256, 1) void ffn1_mma() {
    int e   = blockIdx.z;
    int cnt = g_cnt[e];
    int m0  = blockIdx.y * 128;
    if (m0 >= cnt) return;
    int n0h = blockIdx.x * 128;   // hidden base

    int* s_rows = reinterpret_cast<int*>(dynsmem);
    uint32_t sb = smem_u32(dynsmem) + 1024;

    int tid = threadIdx.x, lane = tid & 31, wid = tid >> 5;
    if (tid < 128) s_rows[tid] = g_list[e * NTOK + min(m0 + tid, cnt - 1)];
    __syncthreads();

    const __half* W1 = g_w1f + (size_t)e * HID * DIMD;
    const __half* W3 = g_w3f + (size_t)e * HID * DIMD;

    float acc[4][8][4];
#pragma unroll
    for (int mt = 0; mt < 4; mt++)
#pragma unroll
        for (int nt = 0; nt < 8; nt++)
#pragma unroll
            for (int q = 0; q < 4; q++) acc[mt][nt][q] = 0.f;

    int wm = (wid >> 2) * 64;
    int wn = (wid & 3) * 64;     // B-tile col offset (= 32 hidden)

    auto load_chunk = [&](uint32_t bb, int k0) {
#pragma unroll
        for (int it = 0; it < 4; it++) {         // A: 128 rows, hi+lo
            int i = tid + it * 256;
            int r = i >> 3, c = i & 7;
            int tok = s_rows[r] >> 1;
            size_t off = (size_t)tok * DIMD + k0 + c * 8;
            cpa(bb + OFF_AH + r * RS + c * 16, g_xh + off);
            cpa(bb + OFF_AL + r * RS + c * 16, g_xl + off);
        }
#pragma unroll
        for (int it = 0; it < 8; it++) {         // B: 256 interleaved rows
            int i = tid + it * 256;
            int r = i >> 3, c = i & 7;
            int j = n0h + (r >> 1);
            const __half* s = (r & 1) ? W3 : W1;
            size_t off = (size_t)j * DIMD + k0 + c * 8;
            cpa(bb + OFF_B + r * RS + c * 16, s + off);
        }
        CPA_COMMIT();
    };

    load_chunk(sb, 0);

    for (int kc = 0; kc < DIMD / 64; kc++) {
        uint32_t bb = sb + (kc & 1) * BUFSZ;
        if (kc + 1 < DIMD / 64) {
            load_chunk(sb + ((kc + 1) & 1) * BUFSZ, (kc + 1) * 64);
            CPA_WAIT1();
        } else {
            CPA_WAIT0();
        }
        __syncthreads();

#pragma unroll
        for (int ks = 0; ks < 4; ks++) {
            uint32_t ah[4][4], al[4][4];
            int arow = wm + (lane & 15);
            int acol = ks * 16 + ((lane >> 4) << 3);
#pragma unroll
            for (int mt = 0; mt < 4; mt++) {
                uint32_t ao = (uint32_t)((arow + mt * 16) * RS + acol * 2);
                ldm_x4(bb + OFF_AH + ao, ah[mt]);
                ldm_x4(bb + OFF_AL + ao, al[mt]);
            }
            int brow = wn + (lane & 7) + ((lane >> 4) << 3);
            int bcol = ks * 16 + ((lane >> 3) & 1) * 8;
#pragma unroll
            for (int ntp = 0; ntp < 4; ntp++) {
                uint32_t bo = (uint32_t)((brow + ntp * 16) * RS + bcol * 2);
                uint32_t b4[4];
                ldm_x4(bb + OFF_B + bo, b4);
                // pass 1: ah x b (8 independent accs)
#pragma unroll
                for (int mt = 0; mt < 4; mt++) mma16816(acc[mt][2*ntp],   ah[mt], b4);
#pragma unroll
                for (int mt = 0; mt < 4; mt++) mma16816(acc[mt][2*ntp+1], ah[mt], b4 + 2);
                // pass 2: al x b
#pragma unroll
                for (int mt = 0; mt < 4; mt++) mma16816(acc[mt][2*ntp],   al[mt], b4);
#pragma unroll
                for (int mt = 0; mt < 4; mt++) mma16816(acc[mt][2*ntp+1], al[mt], b4 + 2);
            }
        }
        __syncthreads();
    }

    // epilogue: c0=w1-dot (even col), c1=w3-dot (odd col), same hidden index.
    uint32_t* HH = reinterpret_cast<uint32_t*>(g_hh);
    uint32_t* HL = reinterpret_cast<uint32_t*>(g_hl);
    int hb = n0h + (wn >> 1) + (lane & 3);   // + nt*4 below
#pragma unroll
    for (int mt = 0; mt < 4; mt++) {
#pragma unroll
        for (int half = 0; half < 2; half++) {
            int mi = wm + mt * 16 + (lane >> 2) + half * 8;
            bool valid = (m0 + mi) < cnt;
            int slot = s_rows[mi];
#pragma unroll
            for (int nt = 0; nt < 8; nt++) {
                float c0 = acc[mt][nt][half * 2];
                float c1 = acc[mt][nt][half * 2 + 1];
                float h = c0 / (1.f + __expf(-c0)) * c1;
                __half Hh = __float2half_rn(h);
                __half Lh = __float2half_rn(h - __half2float(Hh));
                uint32_t hl = pack2h(Hh, Lh);
                uint32_t other = __shfl_xor_sync(0xffffffffu, hl, 1);
                if (!(lane & 1) && valid) {
                    int hidden = hb + nt * 4;            // even
                    size_t idx = ((size_t)slot * HID + hidden) >> 1;
                    HH[idx] = (hl & 0xffffu) | ((other & 0xffffu) << 16);
                    HL[idx] = (hl >> 16) | (other & 0xffff0000u);
                }
            }
        }
    }
}

// =======================================================================
// Stage B: pout = (h @ w2^T) * wt.  Same geometry; A = h hi/lo, B = w2 fp16.
// =======================================================================
__global__ __launch_bounds__(256, 1) void ffn2_mma() {
    int e   = blockIdx.z;
    int cnt = g_cnt[e];
    int m0  = blockIdx.y * 128;
    if (m0 >= cnt) return;
    int n0  = blockIdx.x * 256;

    int* s_rows = reinterpret_cast<int*>(dynsmem);
    uint32_t sb = smem_u32(dynsmem) + 1024;

    int tid = threadIdx.x, lane = tid & 31, wid = tid >> 5;
    if (tid < 128) s_rows[tid] = g_list[e * NTOK + min(m0 + tid, cnt - 1)];
    __syncthreads();

    const __half* W2 = g_w2f + (size_t)e * DIMD * HID;

    float acc[4][8][4];
#pragma unroll
    for (int mt = 0; mt < 4; mt++)
#pragma unroll
        for (int nt = 0; nt < 8; nt++)
#pragma unroll
            for (int q = 0; q < 4; q++) acc[mt][nt][q] = 0.f;

    int wm = (wid >> 2) * 64;
    int wn = (wid & 3) * 64;

    auto load_chunk = [&](uint32_t bb, int k0) {
#pragma unroll
        for (int it = 0; it < 4; it++) {         // A: 128 rows (gathered h)
            int i = tid + it * 256;
            int r = i >> 3, c = i & 7;
            int slot = s_rows[r];
            size_t off = (size_t)slot * HID + k0 + c * 8;
            cpa(bb + OFF_AH + r * RS + c * 16, g_hh + off);
            cpa(bb + OFF_AL + r * RS + c * 16, g_hl + off);
        }
#pragma unroll
        for (int it = 0; it < 8; it++) {         // B: 256 w2 rows
            int i = tid + it * 256;
            int r = i >> 3, c = i & 7;
            size_t off = (size_t)(n0 + r) * HID + k0 + c * 8;
            cpa(bb + OFF_B + r * RS + c * 16, W2 + off);
        }
        CPA_COMMIT();
    };

    load_chunk(sb, 0);

    for (int kc = 0; kc < HID / 64; kc++) {
        uint32_t bb = sb + (kc & 1) * BUFSZ;
        if (kc + 1 < HID / 64) {
            load_chunk(sb + ((kc + 1) & 1) * BUFSZ, (kc + 1) * 64);
            CPA_WAIT1();
        } else {
            CPA_WAIT0();
        }
        __syncthreads();

#pragma unroll
        for (int ks = 0; ks < 4; ks++) {
            uint32_t ah[4][4], al[4][4];
            int arow = wm + (lane & 15);
            int acol = ks * 16 + ((lane >> 4) << 3);
#pragma unroll
            for (int mt = 0; mt < 4; mt++) {
                uint32_t ao = (uint32_t)((arow + mt * 16) * RS + acol * 2);
                ldm_x4(bb + OFF_AH + ao, ah[mt]);
                ldm_x4(bb + OFF_AL + ao, al[mt]);
            }
            int brow = wn + (lane & 7) + ((lane >> 4) << 3);
            int bcol = ks * 16 + ((lane >> 3) & 1) * 8;
#pragma unroll
            for (int ntp = 0; ntp < 4; ntp++) {
                uint32_t bo = (uint32_t)((brow + ntp * 16) * RS + bcol * 2);
                uint32_t b4[4];
                ldm_x4(bb + OFF_B + bo, b4);
                // pass 1: ah x b
#pragma unroll
                for (int mt = 0; mt < 4; mt++) mma16816(acc[mt][2*ntp],   ah[mt], b4);
#pragma unroll
                for (int mt = 0; mt < 4; mt++) mma16816(acc[mt][2*ntp+1], ah[mt], b4 + 2);
                // pass 2: al x b
#pragma unroll
                for (int mt = 0; mt < 4; mt++) mma16816(acc[mt][2*ntp],   al[mt], b4);
#pragma unroll
                for (int mt = 0; mt < 4; mt++) mma16816(acc[mt][2*ntp+1], al[mt], b4 + 2);
            }
        }
        __syncthreads();
    }

    // epilogue: pout = acc * wt[slot]
#pragma unroll
    for (int mt = 0; mt < 4; mt++) {
#pragma unroll
        for (int half = 0; half < 2; half++) {
            int mi = wm + mt * 16 + (lane >> 2) + half * 8;
            if (m0 + mi >= cnt) continue;
            int slot = s_rows[mi];
            float wt = g_wt[slot];
            float* row = g_pout + (size_t)slot * DIMD;
#pragma unroll
            for (int nt = 0; nt < 8; nt++) {
                int gn = n0 + wn + nt * 8 + 2 * (lane & 3);
                float2 v;
                v.x = acc[mt][nt][half * 2] * wt;
                v.y = acc[mt][nt][half * 2 + 1] * wt;
                *reinterpret_cast<float2*>(row + gn) = v;
            }
        }
    }
}

// ---------------- combine ----------------
__global__ void combine_kernel(float* __restrict__ out) {
    size_t i = (size_t)blockIdx.x * blockDim.x + threadIdx.x;
    const size_t Q = DIMD / 4;
    if (i < (size_t)NTOK * Q) {
        size_t t = i / Q, q = i % Q;
        const float4* p = reinterpret_cast<const float4*>(g_pout);
        float4 a = p[(2 * t) * Q + q];
        float4 b = p[(2 * t + 1) * Q + q];
        float4 o;
        o.x = a.x + b.x; o.y = a.y + b.y; o.z = a.z + b.z; o.w = a.w + b.w;
        reinterpret_cast<float4*>(out)[i] = o;
    }
}

// ---------------- launcher ----------------
// Launch order puts ffn1 at index 5 so the harness's fixed `ncu -s 5 -c 1`
// captures the stage-A GEMM: init(0) router(1) cvt_x(2) cvt_w13(3) cvt_w2(4) ffn1(5).
extern "C" void kernel_launch(void* const* d_in, const int* in_sizes, int n_in,
                              void* d_out, int out_size) {
    const float* x  = (const float*)d_in[0];
    const float* gw = (const float*)d_in[1];
    const float* w1 = (const float*)d_in[2];
    const float* w3 = (const float*)d_in[3];
    const float* w2 = (const float*)d_in[4];
    float* out = (float*)d_out;

    __half *xh, *xl, *w1f, *w3f, *w2f;
    cudaGetSymbolAddress((void**)&xh,  g_xh);  cudaGetSymbolAddress((void**)&xl,  g_xl);
    cudaGetSymbolAddress((void**)&w1f, g_w1f); cudaGetSymbolAddress((void**)&w3f, g_w3f);
    cudaGetSymbolAddress((void**)&w2f, g_w2f);

    cudaFuncSetAttribute(ffn1_mma, cudaFuncAttributeMaxDynamicSharedMemorySize, SMEM_TOTAL);
    cudaFuncSetAttribute(ffn2_mma, cudaFuncAttributeMaxDynamicSharedMemorySize, SMEM_TOTAL);

    init_kernel<<<1, 32>>>();
    router_kernel<<<NTOK / 8, 256>>>(x, gw);

    int xn4 = NTOK * DIMD / 4;
    int wn4 = (int)(WN / 4);
    cvt_x_kernel<<<(xn4 + 255) / 256, 256>>>(x, xh, xl, xn4);
    cvt_w2x_kernel<<<dim3((wn4 + 255) / 256, 1, 2), 256>>>(w1, w1f, w3, w3f, wn4);
    cvt_w2x_kernel<<<dim3((wn4 + 255) / 256, 1, 1), 256>>>(w2, w2f, w2, w2f, wn4);

    ffn1_mma<<<dim3(HID / 128, NTOK / 128, NEXP), 256, SMEM_TOTAL>>>();
    ffn2_mma<<<dim3(DIMD / 256, NTOK / 128, NEXP), 256, SMEM_TOTAL>>>();
    combine_kernel<<<(NTOK * (DIMD / 4) + 255) / 256, 256>>>(out);
}

// round 14
// speedup vs baseline: 2.1573x; 1.5418x over previous
#include <cuda_runtime.h>
#include <cuda_fp16.h>
#include <cstdint>
#include <math.h>

// ---------------- problem constants ----------------
#define NTOK 8192      // B*T
#define DIMD 1024
#define NEXP 8
#define HID  2816
#define NPAIR (2*NTOK)
#define WN   ((size_t)NEXP*HID*DIMD)

// ---------------- device scratch (static; allocations forbidden) ----------------
__device__ __half g_w1f[WN], g_w3f[WN], g_w2f[WN];       // fp16 weights
__device__ __half g_xf[(size_t)NTOK*DIMD];               // fp16 x
__device__ __half g_hf[(size_t)NPAIR*HID];               // fp16 h
__device__ float g_pout[(size_t)NPAIR*DIMD];
__device__ int   g_list[NEXP*NTOK];
__device__ float g_wt[NPAIR];
__device__ int   g_cnt[NEXP];

// ---------------- PTX helpers (base PTX only: sm_80+ features) ----------------
static __device__ __forceinline__ uint32_t smem_u32(const void* p) {
    uint32_t a;
    asm("{ .reg .u64 t; cvta.to.shared.u64 t, %1; cvt.u32.u64 %0, t; }" : "=r"(a) : "l"(p));
    return a;
}
static __device__ __forceinline__ void cpa(uint32_t dst, const void* src) {
    asm volatile("cp.async.cg.shared.global [%0], [%1], 16;" :: "r"(dst), "l"(src) : "memory");
}
#define CPA_COMMIT() asm volatile("cp.async.commit_group;" ::: "memory")
#define CPA_WAIT1()  asm volatile("cp.async.wait_group 1;" ::: "memory")
#define CPA_WAIT0()  asm volatile("cp.async.wait_group 0;" ::: "memory")

static __device__ __forceinline__ void ldm_x4(uint32_t a, uint32_t* r) {
    asm volatile("ldmatrix.sync.aligned.m8n8.x4.shared.b16 {%0,%1,%2,%3}, [%4];"
        : "=r"(r[0]), "=r"(r[1]), "=r"(r[2]), "=r"(r[3]) : "r"(a));
}
static __device__ __forceinline__ void mma16816(float* c, const uint32_t* a, const uint32_t* b) {
    asm volatile("mma.sync.aligned.m16n8k16.row.col.f32.f16.f16.f32 "
        "{%0,%1,%2,%3}, {%4,%5,%6,%7}, {%8,%9}, {%0,%1,%2,%3};"
        : "+f"(c[0]), "+f"(c[1]), "+f"(c[2]), "+f"(c[3])
        : "r"(a[0]), "r"(a[1]), "r"(a[2]), "r"(a[3]), "r"(b[0]), "r"(b[1]));
}
static __device__ __forceinline__ uint32_t pack2h(__half a, __half b) {
    return (uint32_t)__half_as_ushort(a) | ((uint32_t)__half_as_ushort(b) << 16);
}

// smem row stride: 72 fp16 = 144B. Rows rotate 16B mod 128B -> ldmatrix conflict-free.
#define RS 144

// Unified GEMM geometry: CTA M=128 x N=256 (B-tile rows), 8 warps as 2(M)x4(N):
// warp tile 64M x 64N (mt=4, nt=8). K-chunk 64, double-buffered. Pure fp16, 1 pass.
#define OFF_A 0
#define OFF_B 18432
#define BUFSZ 55296
#define SMEM_TOTAL (1024 + 2*BUFSZ)   // 111616

// ---------------- small kernels ----------------
__global__ void init_kernel() {
    if (threadIdx.x < NEXP) g_cnt[threadIdx.x] = 0;
}

// fp32 -> fp16 (single tensor)
__global__ void cvt_f16_kernel(const float* __restrict__ src,
                               __half* __restrict__ dst, int n4) {
    int i = blockIdx.x * blockDim.x + threadIdx.x;
    if (i >= n4) return;
    float4 v = reinterpret_cast<const float4*>(src)[i];
    uint2 H;
    H.x = pack2h(__float2half_rn(v.x), __float2half_rn(v.y));
    H.y = pack2h(__float2half_rn(v.z), __float2half_rn(v.w));
    reinterpret_cast<uint2*>(dst)[i] = H;
}

// fp32 -> fp16, two tensors via blockIdx.z
__global__ void cvt_w2x_kernel(const float* __restrict__ s0, __half* __restrict__ d0,
                               const float* __restrict__ s1, __half* __restrict__ d1,
                               int n4) {
    int i = blockIdx.x * blockDim.x + threadIdx.x;
    if (i >= n4) return;
    const float* src = blockIdx.z ? s1 : s0;
    __half* dst = blockIdx.z ? d1 : d0;
    float4 v = reinterpret_cast<const float4*>(src)[i];
    uint2 H;
    H.x = pack2h(__float2half_rn(v.x), __float2half_rn(v.y));
    H.y = pack2h(__float2half_rn(v.z), __float2half_rn(v.w));
    reinterpret_cast<uint2*>(dst)[i] = H;
}

__global__ void router_kernel(const float* __restrict__ x,
                              const float* __restrict__ gw) {
    int w    = (blockIdx.x * blockDim.x + threadIdx.x) >> 5;
    int lane = threadIdx.x & 31;
    if (w >= NTOK) return;
    const float* xr = x + (size_t)w * DIMD;
    float acc[NEXP];
#pragma unroll
    for (int e = 0; e < NEXP; e++) acc[e] = 0.f;
    for (int d = lane; d < DIMD; d += 32) {
        float xv = xr[d];
#pragma unroll
        for (int e = 0; e < NEXP; e++) acc[e] += xv * gw[e * DIMD + d];
    }
#pragma unroll
    for (int e = 0; e < NEXP; e++)
#pragma unroll
        for (int o = 16; o > 0; o >>= 1)
            acc[e] += __shfl_xor_sync(0xffffffffu, acc[e], o);
    if (lane == 0) {
        float m = acc[0];
#pragma unroll
        for (int e = 1; e < NEXP; e++) m = fmaxf(m, acc[e]);
        float p[NEXP];
#pragma unroll
        for (int e = 0; e < NEXP; e++) p[e] = __expf(acc[e] - m);
        int i0 = 0; float b0 = p[0];
#pragma unroll
        for (int e = 1; e < NEXP; e++) if (p[e] > b0) { b0 = p[e]; i0 = e; }
        int i1 = -1; float b1 = -1.f;
#pragma unroll
        for (int e = 0; e < NEXP; e++) if (e != i0 && p[e] > b1) { b1 = p[e]; i1 = e; }
        float s = b0 + b1;
        g_wt[2 * w]     = b0 / s;
        g_wt[2 * w + 1] = b1 / s;
        int pos0 = atomicAdd(&g_cnt[i0], 1);
        g_list[i0 * NTOK + pos0] = 2 * w;
        int pos1 = atomicAdd(&g_cnt[i1], 1);
        g_list[i1 * NTOK + pos1] = 2 * w + 1;
    }
}

extern __shared__ char dynsmem[];

// =======================================================================
// Stage A: single fp16 GEMM, w1/w3 rows interleaved in B tile.
// Output col pair even/odd = (w1-dot, w3-dot) of the same hidden index.
// =======================================================================
__global__ __launch_bounds__(256, 1) void ffn1_mma() {
    int e   = blockIdx.z;
    int cnt = g_cnt[e];
    int m0  = blockIdx.y * 128;
    if (m0 >= cnt) return;
    int n0h = blockIdx.x * 128;   // hidden base

    int* s_rows = reinterpret_cast<int*>(dynsmem);
    uint32_t sb = smem_u32(dynsmem) + 1024;

    int tid = threadIdx.x, lane = tid & 31, wid = tid >> 5;
    if (tid < 128) s_rows[tid] = g_list[e * NTOK + min(m0 + tid, cnt - 1)];
    __syncthreads();

    const __half* W1 = g_w1f + (size_t)e * HID * DIMD;
    const __half* W3 = g_w3f + (size_t)e * HID * DIMD;

    float acc[4][8][4];
#pragma unroll
    for (int mt = 0; mt < 4; mt++)
#pragma unroll
        for (int nt = 0; nt < 8; nt++)
#pragma unroll
            for (int q = 0; q < 4; q++) acc[mt][nt][q] = 0.f;

    int wm = (wid >> 2) * 64;
    int wn = (wid & 3) * 64;     // B-tile col offset (= 32 hidden)

    auto load_chunk = [&](uint32_t bb, int k0) {
#pragma unroll
        for (int it = 0; it < 4; it++) {         // A: 128 rows fp16
            int i = tid + it * 256;
            int r = i >> 3, c = i & 7;
            int tok = s_rows[r] >> 1;
            cpa(bb + OFF_A + r * RS + c * 16, g_xf + (size_t)tok * DIMD + k0 + c * 8);
        }
#pragma unroll
        for (int it = 0; it < 8; it++) {         // B: 256 interleaved rows
            int i = tid + it * 256;
            int r = i >> 3, c = i & 7;
            int j = n0h + (r >> 1);
            const __half* s = (r & 1) ? W3 : W1;
            cpa(bb + OFF_B + r * RS + c * 16, s + (size_t)j * DIMD + k0 + c * 8);
        }
        CPA_COMMIT();
    };

    load_chunk(sb, 0);

    for (int kc = 0; kc < DIMD / 64; kc++) {
        uint32_t bb = sb + (kc & 1) * BUFSZ;
        if (kc + 1 < DIMD / 64) {
            load_chunk(sb + ((kc + 1) & 1) * BUFSZ, (kc + 1) * 64);
            CPA_WAIT1();
        } else {
            CPA_WAIT0();
        }
        __syncthreads();

#pragma unroll
        for (int ks = 0; ks < 4; ks++) {
            uint32_t ah[4][4];
            int arow = wm + (lane & 15);
            int acol = ks * 16 + ((lane >> 4) << 3);
#pragma unroll
            for (int mt = 0; mt < 4; mt++) {
                uint32_t ao = (uint32_t)((arow + mt * 16) * RS + acol * 2);
                ldm_x4(bb + OFF_A + ao, ah[mt]);
            }
            int brow = wn + (lane & 7) + ((lane >> 4) << 3);
            int bcol = ks * 16 + ((lane >> 3) & 1) * 8;
#pragma unroll
            for (int ntp = 0; ntp < 4; ntp++) {
                uint32_t bo = (uint32_t)((brow + ntp * 16) * RS + bcol * 2);
                uint32_t b4[4];
                ldm_x4(bb + OFF_B + bo, b4);
#pragma unroll
                for (int mt = 0; mt < 4; mt++) mma16816(acc[mt][2*ntp],   ah[mt], b4);
#pragma unroll
                for (int mt = 0; mt < 4; mt++) mma16816(acc[mt][2*ntp+1], ah[mt], b4 + 2);
            }
        }
        __syncthreads();
    }

    // epilogue: c0=w1-dot (even col), c1=w3-dot (odd col), same hidden index.
    // pair even/odd hidden via shfl_xor(1); even lanes issue 4B stores.
    uint32_t* HF = reinterpret_cast<uint32_t*>(g_hf);
    int hb = n0h + (wn >> 1) + (lane & 3);   // + nt*4 below
#pragma unroll
    for (int mt = 0; mt < 4; mt++) {
#pragma unroll
        for (int half = 0; half < 2; half++) {
            int mi = wm + mt * 16 + (lane >> 2) + half * 8;
            bool valid = (m0 + mi) < cnt;
            int slot = s_rows[mi];
#pragma unroll
            for (int nt = 0; nt < 8; nt++) {
                float c0 = acc[mt][nt][half * 2];
                float c1 = acc[mt][nt][half * 2 + 1];
                float h = c0 / (1.f + __expf(-c0)) * c1;
                uint32_t v = (uint32_t)__half_as_ushort(__float2half_rn(h));
                uint32_t other = __shfl_xor_sync(0xffffffffu, v, 1);
                if (!(lane & 1) && valid) {
                    int hidden = hb + nt * 4;            // even
                    size_t idx = ((size_t)slot * HID + hidden) >> 1;
                    HF[idx] = v | (other << 16);
                }
            }
        }
    }
}

// =======================================================================
// Stage B: pout = (h @ w2^T) * wt.  Pure fp16, 1 pass.
// =======================================================================
__global__ __launch_bounds__(256, 1) void ffn2_mma() {
    int e   = blockIdx.z;
    int cnt = g_cnt[e];
    int m0  = blockIdx.y * 128;
    if (m0 >= cnt) return;
    int n0  = blockIdx.x * 256;

    int* s_rows = reinterpret_cast<int*>(dynsmem);
    uint32_t sb = smem_u32(dynsmem) + 1024;

    int tid = threadIdx.x, lane = tid & 31, wid = tid >> 5;
    if (tid < 128) s_rows[tid] = g_list[e * NTOK + min(m0 + tid, cnt - 1)];
    __syncthreads();

    const __half* W2 = g_w2f + (size_t)e * DIMD * HID;

    float acc[4][8][4];
#pragma unroll
    for (int mt = 0; mt < 4; mt++)
#pragma unroll
        for (int nt = 0; nt < 8; nt++)
#pragma unroll
            for (int q = 0; q < 4; q++) acc[mt][nt][q] = 0.f;

    int wm = (wid >> 2) * 64;
    int wn = (wid & 3) * 64;

    auto load_chunk = [&](uint32_t bb, int k0) {
#pragma unroll
        for (int it = 0; it < 4; it++) {         // A: 128 rows (gathered h)
            int i = tid + it * 256;
            int r = i >> 3, c = i & 7;
            int slot = s_rows[r];
            cpa(bb + OFF_A + r * RS + c * 16, g_hf + (size_t)slot * HID + k0 + c * 8);
        }
#pragma unroll
        for (int it = 0; it < 8; it++) {         // B: 256 w2 rows
            int i = tid + it * 256;
            int r = i >> 3, c = i & 7;
            cpa(bb + OFF_B + r * RS + c * 16, W2 + (size_t)(n0 + r) * HID + k0 + c * 8);
        }
        CPA_COMMIT();
    };

    load_chunk(sb, 0);

    for (int kc = 0; kc < HID / 64; kc++) {
        uint32_t bb = sb + (kc & 1) * BUFSZ;
        if (kc + 1 < HID / 64) {
            load_chunk(sb + ((kc + 1) & 1) * BUFSZ, (kc + 1) * 64);
            CPA_WAIT1();
        } else {
            CPA_WAIT0();
        }
        __syncthreads();

#pragma unroll
        for (int ks = 0; ks < 4; ks++) {
            uint32_t ah[4][4];
            int arow = wm + (lane & 15);
            int acol = ks * 16 + ((lane >> 4) << 3);
#pragma unroll
            for (int mt = 0; mt < 4; mt++) {
                uint32_t ao = (uint32_t)((arow + mt * 16) * RS + acol * 2);
                ldm_x4(bb + OFF_A + ao, ah[mt]);
            }
            int brow = wn + (lane & 7) + ((lane >> 4) << 3);
            int bcol = ks * 16 + ((lane >> 3) & 1) * 8;
#pragma unroll
            for (int ntp = 0; ntp < 4; ntp++) {
                uint32_t bo = (uint32_t)((brow + ntp * 16) * RS + bcol * 2);
                uint32_t b4[4];
                ldm_x4(bb + OFF_B + bo, b4);
#pragma unroll
                for (int mt = 0; mt < 4; mt++) mma16816(acc[mt][2*ntp],   ah[mt], b4);
#pragma unroll
                for (int mt = 0; mt < 4; mt++) mma16816(acc[mt][2*ntp+1], ah[mt], b4 + 2);
            }
        }
        __syncthreads();
    }

    // epilogue: pout = acc * wt[slot]
#pragma unroll
    for (int mt = 0; mt < 4; mt++) {
#pragma unroll
        for (int half = 0; half < 2; half++) {
            int mi = wm + mt * 16 + (lane >> 2) + half * 8;
            if (m0 + mi >= cnt) continue;
            int slot = s_rows[mi];
            float wt = g_wt[slot];
            float* row = g_pout + (size_t)slot * DIMD;
#pragma unroll
            for (int nt = 0; nt < 8; nt++) {
                int gn = n0 + wn + nt * 8 + 2 * (lane & 3);
                float2 v;
                v.x = acc[mt][nt][half * 2] * wt;
                v.y = acc[mt][nt][half * 2 + 1] * wt;
                *reinterpret_cast<float2*>(row + gn) = v;
            }
        }
    }
}

// ---------------- combine ----------------
__global__ void combine_kernel(float* __restrict__ out) {
    size_t i = (size_t)blockIdx.x * blockDim.x + threadIdx.x;
    const size_t Q = DIMD / 4;
    if (i < (size_t)NTOK * Q) {
        size_t t = i / Q, q = i % Q;
        const float4* p = reinterpret_cast<const float4*>(g_pout);
        float4 a = p[(2 * t) * Q + q];
        float4 b = p[(2 * t + 1) * Q + q];
        float4 o;
        o.x = a.x + b.x; o.y = a.y + b.y; o.z = a.z + b.z; o.w = a.w + b.w;
        reinterpret_cast<float4*>(out)[i] = o;
    }
}

// ---------------- launcher ----------------
// ffn1 at launch index 5 so the harness's fixed `ncu -s 5 -c 1` captures it:
// init(0) router(1) cvt_x(2) cvt_w13(3) cvt_w2(4) ffn1(5).
extern "C" void kernel_launch(void* const* d_in, const int* in_sizes, int n_in,
                              void* d_out, int out_size) {
    const float* x  = (const float*)d_in[0];
    const float* gw = (const float*)d_in[1];
    const float* w1 = (const float*)d_in[2];
    const float* w3 = (const float*)d_in[3];
    const float* w2 = (const float*)d_in[4];
    float* out = (float*)d_out;

    __half *xf, *w1f, *w3f, *w2f;
    cudaGetSymbolAddress((void**)&xf,  g_xf);
    cudaGetSymbolAddress((void**)&w1f, g_w1f); cudaGetSymbolAddress((void**)&w3f, g_w3f);
    cudaGetSymbolAddress((void**)&w2f, g_w2f);

    cudaFuncSetAttribute(ffn1_mma, cudaFuncAttributeMaxDynamicSharedMemorySize, SMEM_TOTAL);
    cudaFuncSetAttribute(ffn2_mma, cudaFuncAttributeMaxDynamicSharedMemorySize, SMEM_TOTAL);

    init_kernel<<<1, 32>>>();
    router_kernel<<<NTOK / 8, 256>>>(x, gw);

    int xn4 = NTOK * DIMD / 4;
    int wn4 = (int)(WN / 4);
    cvt_f16_kernel<<<(xn4 + 255) / 256, 256>>>(x, xf, xn4);
    cvt_w2x_kernel<<<dim3((wn4 + 255) / 256, 1, 2), 256>>>(w1, w1f, w3, w3f, wn4);
    cvt_w2x_kernel<<<dim3((wn4 + 255) / 256, 1, 1), 256>>>(w2, w2f, w2, w2f, wn4);

    ffn1_mma<<<dim3(HID / 128, NTOK / 128, NEXP), 256, SMEM_TOTAL>>>();
    ffn2_mma<<<dim3(DIMD / 256, NTOK / 128, NEXP), 256, SMEM_TOTAL>>>();
    combine_kernel<<<(NTOK * (DIMD / 4) + 255) / 256, 256>>>(out);
}